// round 1
// baseline (speedup 1.0000x reference)
#include <cuda_runtime.h>
#include <math.h>

// Problem constants
#define B_  2
#define S_  2048
#define H_  1024
#define NH_ 16
#define HD_ 64
#define ROWS_ (B_ * S_)          // 4096

// Scratch (device globals: allocation-free)
__device__ float g_Q[ROWS_ * H_];
__device__ float g_K[ROWS_ * H_];
__device__ float g_V[ROWS_ * H_];
__device__ float g_CTX[ROWS_ * H_];
__device__ float g_O[ROWS_ * H_];

// ---------------------------------------------------------------------------
// SGEMM: C[M,N] = A[M,K] @ W[K,N] + bias[N]
// 128x128 block tile, BK=8, 256 threads, 8x8 per-thread micro tile.
// ---------------------------------------------------------------------------
__global__ __launch_bounds__(256) void sgemm_bias(
    const float* __restrict__ A, const float* __restrict__ W,
    const float* __restrict__ bias, float* __restrict__ C,
    int M, int N, int K)
{
    __shared__ float As[8][128];   // As[k][m] (transposed)
    __shared__ float Bs[8][128];   // Bs[k][n]

    const int tid = threadIdx.x;
    const int tx = tid & 15;       // 0..15 -> column micro group
    const int ty = tid >> 4;       // 0..15 -> row micro group
    const int rowBase = blockIdx.y * 128;
    const int colBase = blockIdx.x * 128;

    // A tile load mapping: 128x8 floats, one float4 per thread
    const int aRow = tid >> 1;           // 0..127
    const int aCol = (tid & 1) * 4;      // 0 or 4
    // W tile load mapping: 8x128 floats, one float4 per thread
    const int bRow = tid >> 5;           // 0..7
    const int bCol = (tid & 31) * 4;     // 0..124

    const float* Aptr = A + (size_t)(rowBase + aRow) * K + aCol;
    const float* Wptr = W + (size_t)bRow * N + colBase + bCol;

    float acc[8][8];
#pragma unroll
    for (int i = 0; i < 8; i++)
#pragma unroll
        for (int j = 0; j < 8; j++) acc[i][j] = 0.f;

    for (int k0 = 0; k0 < K; k0 += 8) {
        float4 a4 = *(const float4*)(Aptr + k0);
        float4 b4 = *(const float4*)(Wptr + (size_t)k0 * N);

        __syncthreads();  // previous tile fully consumed
        As[aCol + 0][aRow] = a4.x;
        As[aCol + 1][aRow] = a4.y;
        As[aCol + 2][aRow] = a4.z;
        As[aCol + 3][aRow] = a4.w;
        *(float4*)&Bs[bRow][bCol] = b4;
        __syncthreads();

#pragma unroll
        for (int kk = 0; kk < 8; kk++) {
            float ar[8], br[8];
            *(float4*)(ar)     = *(const float4*)&As[kk][ty * 8];
            *(float4*)(ar + 4) = *(const float4*)&As[kk][ty * 8 + 4];
            *(float4*)(br)     = *(const float4*)&Bs[kk][tx * 8];
            *(float4*)(br + 4) = *(const float4*)&Bs[kk][tx * 8 + 4];
#pragma unroll
            for (int i = 0; i < 8; i++)
#pragma unroll
                for (int j = 0; j < 8; j++)
                    acc[i][j] = fmaf(ar[i], br[j], acc[i][j]);
        }
    }

    // Epilogue: add bias, store
    float bvals[8];
#pragma unroll
    for (int j = 0; j < 8; j++) bvals[j] = bias[colBase + tx * 8 + j];

#pragma unroll
    for (int i = 0; i < 8; i++) {
        int row = rowBase + ty * 8 + i;
        float* cp = C + (size_t)row * N + colBase + tx * 8;
        float4 o0, o1;
        o0.x = acc[i][0] + bvals[0];
        o0.y = acc[i][1] + bvals[1];
        o0.z = acc[i][2] + bvals[2];
        o0.w = acc[i][3] + bvals[3];
        o1.x = acc[i][4] + bvals[4];
        o1.y = acc[i][5] + bvals[5];
        o1.z = acc[i][6] + bvals[6];
        o1.w = acc[i][7] + bvals[7];
        *(float4*)(cp)     = o0;
        *(float4*)(cp + 4) = o1;
    }
}

// ---------------------------------------------------------------------------
// Flash attention (fp32): one block = 64 queries of one (b,h); one thread = 1 query.
// q vector + ctx accumulator live in registers; K/V tiles (64x64) in smem,
// read with full-warp broadcast (conflict-free).
// ---------------------------------------------------------------------------
__global__ __launch_bounds__(64) void attn_kernel(
    const float* __restrict__ Q, const float* __restrict__ K,
    const float* __restrict__ V, const float* __restrict__ mask,
    float* __restrict__ CTX)
{
    const int b = blockIdx.z;
    const int h = blockIdx.y;
    const int t = threadIdx.x;            // 0..63
    const int q = blockIdx.x * 64 + t;

    __shared__ float ks[64][64];
    __shared__ float vs[64][64];
    __shared__ float mk[64];

    const float* qp = Q + (size_t)(b * S_ + q) * H_ + h * HD_;
    float qv[64];
#pragma unroll
    for (int d = 0; d < 64; d += 4) {
        float4 f = *(const float4*)(qp + d);
        qv[d] = f.x; qv[d + 1] = f.y; qv[d + 2] = f.z; qv[d + 3] = f.w;
    }

    float m = -1e30f, l = 0.f;
    float acc[64];
#pragma unroll
    for (int d = 0; d < 64; d++) acc[d] = 0.f;

    const float* kbase = K + (size_t)(b * S_) * H_ + h * HD_;
    const float* vbase = V + (size_t)(b * S_) * H_ + h * HD_;

    for (int k0 = 0; k0 < S_; k0 += 64) {
        __syncthreads();
        const float* krow = kbase + (size_t)(k0 + t) * H_;
        const float* vrow = vbase + (size_t)(k0 + t) * H_;
#pragma unroll
        for (int d = 0; d < 64; d += 4) {
            *(float4*)&ks[t][d] = *(const float4*)(krow + d);
            *(float4*)&vs[t][d] = *(const float4*)(vrow + d);
        }
        mk[t] = mask[b * S_ + k0 + t];
        __syncthreads();

        for (int j = 0; j < 64; j++) {
            // dot(q, k_j) with 4-way ILP
            float s0 = 0.f, s1 = 0.f, s2 = 0.f, s3 = 0.f;
#pragma unroll
            for (int d = 0; d < 64; d += 4) {
                s0 = fmaf(qv[d],     ks[j][d],     s0);
                s1 = fmaf(qv[d + 1], ks[j][d + 1], s1);
                s2 = fmaf(qv[d + 2], ks[j][d + 2], s2);
                s3 = fmaf(qv[d + 3], ks[j][d + 3], s3);
            }
            float s = (s0 + s1) + (s2 + s3);
            s = s * 0.125f + mk[j];     // /sqrt(64) + mask

            if (s > m) {
                float cor = __expf(m - s);
                l *= cor;
#pragma unroll
                for (int d = 0; d < 64; d++) acc[d] *= cor;
                m = s;
            }
            float p = __expf(s - m);
            l += p;
#pragma unroll
            for (int d = 0; d < 64; d++)
                acc[d] = fmaf(p, vs[j][d], acc[d]);
        }
    }

    float inv = 1.f / l;
    float* op = CTX + (size_t)(b * S_ + q) * H_ + h * HD_;
#pragma unroll
    for (int d = 0; d < 64; d += 4) {
        float4 o;
        o.x = acc[d] * inv; o.y = acc[d + 1] * inv;
        o.z = acc[d + 2] * inv; o.w = acc[d + 3] * inv;
        *(float4*)(op + d) = o;
    }
}

// ---------------------------------------------------------------------------
// Residual add + LayerNorm (eps 1e-12). One block per row (H=1024), 256 thr.
// ---------------------------------------------------------------------------
__device__ __forceinline__ float warp_sum(float v) {
#pragma unroll
    for (int o = 16; o > 0; o >>= 1) v += __shfl_xor_sync(0xffffffffu, v, o);
    return v;
}

__global__ __launch_bounds__(256) void resid_ln(
    const float* __restrict__ X, const float* __restrict__ R,
    const float* __restrict__ gamma, const float* __restrict__ beta,
    float* __restrict__ out)
{
    const int row = blockIdx.x;
    const int t = threadIdx.x;
    const float* x = X + (size_t)row * H_;
    const float* r = R + (size_t)row * H_;

    float4 xv = *(const float4*)(x + t * 4);
    float4 rv = *(const float4*)(r + t * 4);
    float v[4] = { xv.x + rv.x, xv.y + rv.y, xv.z + rv.z, xv.w + rv.w };

    float s = v[0] + v[1] + v[2] + v[3];
    float s2 = v[0] * v[0] + v[1] * v[1] + v[2] * v[2] + v[3] * v[3];

    __shared__ float red1[8], red2[8];
    float ws = warp_sum(s), ws2 = warp_sum(s2);
    int wid = t >> 5, lid = t & 31;
    if (lid == 0) { red1[wid] = ws; red2[wid] = ws2; }
    __syncthreads();
    if (wid == 0) {
        float a = (lid < 8) ? red1[lid] : 0.f;
        float b2 = (lid < 8) ? red2[lid] : 0.f;
        a = warp_sum(a); b2 = warp_sum(b2);
        if (lid == 0) { red1[0] = a; red2[0] = b2; }
    }
    __syncthreads();

    float mean = red1[0] * (1.f / H_);
    float var = red2[0] * (1.f / H_) - mean * mean;
    float rstd = rsqrtf(var + 1e-12f);

    float4 g4 = *(const float4*)(gamma + t * 4);
    float4 b4 = *(const float4*)(beta + t * 4);
    float4 o;
    o.x = (v[0] - mean) * rstd * g4.x + b4.x;
    o.y = (v[1] - mean) * rstd * g4.y + b4.y;
    o.z = (v[2] - mean) * rstd * g4.z + b4.z;
    o.w = (v[3] - mean) * rstd * g4.w + b4.w;
    *(float4*)(out + (size_t)row * H_ + t * 4) = o;
}

// ---------------------------------------------------------------------------
// Launch
// ---------------------------------------------------------------------------
extern "C" void kernel_launch(void* const* d_in, const int* in_sizes, int n_in,
                              void* d_out, int out_size)
{
    const float* hidden = (const float*)d_in[0];
    const float* mask   = (const float*)d_in[1];
    const float* Wq = (const float*)d_in[2];
    const float* bq = (const float*)d_in[3];
    const float* Wk = (const float*)d_in[4];
    const float* bk = (const float*)d_in[5];
    const float* Wv = (const float*)d_in[6];
    const float* bv = (const float*)d_in[7];
    const float* Wo = (const float*)d_in[8];
    const float* bo = (const float*)d_in[9];
    const float* gamma = (const float*)d_in[10];
    const float* beta  = (const float*)d_in[11];
    float* out = (float*)d_out;

    float *Q, *K, *V, *CTX, *O;
    cudaGetSymbolAddress((void**)&Q,   g_Q);
    cudaGetSymbolAddress((void**)&K,   g_K);
    cudaGetSymbolAddress((void**)&V,   g_V);
    cudaGetSymbolAddress((void**)&CTX, g_CTX);
    cudaGetSymbolAddress((void**)&O,   g_O);

    dim3 ggrid(H_ / 128, ROWS_ / 128);   // (8, 32)
    sgemm_bias<<<ggrid, 256>>>(hidden, Wq, bq, Q, ROWS_, H_, H_);
    sgemm_bias<<<ggrid, 256>>>(hidden, Wk, bk, K, ROWS_, H_, H_);
    sgemm_bias<<<ggrid, 256>>>(hidden, Wv, bv, V, ROWS_, H_, H_);

    dim3 agrid(S_ / 64, NH_, B_);        // (32, 16, 2)
    attn_kernel<<<agrid, 64>>>(Q, K, V, mask, CTX);

    sgemm_bias<<<ggrid, 256>>>(CTX, Wo, bo, O, ROWS_, H_, H_);

    resid_ln<<<ROWS_, 256>>>(O, hidden, gamma, beta, out);
}

// round 3
// speedup vs baseline: 1.1623x; 1.1623x over previous
#include <cuda_runtime.h>
#include <cuda_bf16.h>
#include <math.h>
#include <stdint.h>

// Problem constants
#define B_  2
#define S_  2048
#define H_  1024
#define NH_ 16
#define HD_ 64
#define ROWS_ (B_ * S_)          // 4096

// Scratch (device globals: allocation-free)
__device__ float g_Q[ROWS_ * H_];
__device__ float g_K[ROWS_ * H_];
__device__ float g_V[ROWS_ * H_];
__device__ float g_CTX[ROWS_ * H_];
__device__ float g_O[ROWS_ * H_];
__device__ __nv_bfloat16 g_Ahi[ROWS_ * H_];
__device__ __nv_bfloat16 g_Alo[ROWS_ * H_];
__device__ __nv_bfloat16 g_Whi[H_ * H_];
__device__ __nv_bfloat16 g_Wlo[H_ * H_];

// ---------------------------------------------------------------------------
// PTX helpers (Ampere-class: mma.sync / ldmatrix / cp.async — valid on compute_100)
// ---------------------------------------------------------------------------
__device__ __forceinline__ uint32_t smem_u32(const void* p) {
    uint32_t a;
    asm("{ .reg .u64 t; cvta.to.shared.u64 t, %1; cvt.u32.u64 %0, t; }" : "=r"(a) : "l"(p));
    return a;
}
#define CP16(dst, src) \
    asm volatile("cp.async.cg.shared.global [%0], [%1], 16;" :: "r"(dst), "l"(src))
#define CP_COMMIT() asm volatile("cp.async.commit_group;" ::: "memory")
#define CP_WAIT1()  asm volatile("cp.async.wait_group 1;" ::: "memory")

#define LDSM4(r, a) \
    asm volatile("ldmatrix.sync.aligned.m8n8.x4.shared.b16 {%0,%1,%2,%3}, [%4];" \
                 : "=r"((r)[0]), "=r"((r)[1]), "=r"((r)[2]), "=r"((r)[3]) : "r"(a))

#define MMA_BF16(d, a, b0, b1) \
    asm volatile("mma.sync.aligned.m16n8k16.row.col.f32.bf16.bf16.f32 " \
                 "{%0,%1,%2,%3}, {%4,%5,%6,%7}, {%8,%9}, {%0,%1,%2,%3};" \
                 : "+f"((d)[0]), "+f"((d)[1]), "+f"((d)[2]), "+f"((d)[3]) \
                 : "r"((a)[0]), "r"((a)[1]), "r"((a)[2]), "r"((a)[3]), "r"(b0), "r"(b1))

// ---------------------------------------------------------------------------
// Split fp32 -> bf16 hi/lo
// ---------------------------------------------------------------------------
__global__ __launch_bounds__(256) void split_fp32(
    const float* __restrict__ X, __nv_bfloat16* __restrict__ hi,
    __nv_bfloat16* __restrict__ lo, int n4)
{
    int i = blockIdx.x * blockDim.x + threadIdx.x;
    if (i >= n4) return;
    float4 x = *(const float4*)(X + i * 4);
    __nv_bfloat16 h0 = __float2bfloat16(x.x);
    __nv_bfloat16 h1 = __float2bfloat16(x.y);
    __nv_bfloat16 h2 = __float2bfloat16(x.z);
    __nv_bfloat16 h3 = __float2bfloat16(x.w);
    __nv_bfloat162 hp0; hp0.x = h0; hp0.y = h1;
    __nv_bfloat162 hp1; hp1.x = h2; hp1.y = h3;
    __nv_bfloat162 lp0, lp1;
    lp0.x = __float2bfloat16(x.x - __bfloat162float(h0));
    lp0.y = __float2bfloat16(x.y - __bfloat162float(h1));
    lp1.x = __float2bfloat16(x.z - __bfloat162float(h2));
    lp1.y = __float2bfloat16(x.w - __bfloat162float(h3));
    *(__nv_bfloat162*)(hi + i * 4)     = hp0;
    *(__nv_bfloat162*)(hi + i * 4 + 2) = hp1;
    *(__nv_bfloat162*)(lo + i * 4)     = lp0;
    *(__nv_bfloat162*)(lo + i * 4 + 2) = lp1;
}

// ---------------------------------------------------------------------------
// Split + transpose W[K,N] -> Wt_hi/Wt_lo [N,K] (bf16, K-contiguous)
// ---------------------------------------------------------------------------
__global__ __launch_bounds__(256) void split_transpose(
    const float* __restrict__ W, __nv_bfloat16* __restrict__ Thi,
    __nv_bfloat16* __restrict__ Tlo)
{
    __shared__ float t[32][33];
    const int n0 = blockIdx.x * 32, k0 = blockIdx.y * 32;
    const int tx = threadIdx.x, ty = threadIdx.y;   // (32, 8)
#pragma unroll
    for (int r = 0; r < 32; r += 8)
        t[ty + r][tx] = W[(size_t)(k0 + ty + r) * H_ + n0 + tx];
    __syncthreads();
#pragma unroll
    for (int r = 0; r < 32; r += 8) {
        int n = n0 + ty + r, k = k0 + tx;
        float x = t[tx][ty + r];
        __nv_bfloat16 h = __float2bfloat16(x);
        Thi[(size_t)n * H_ + k] = h;
        Tlo[(size_t)n * H_ + k] = __float2bfloat16(x - __bfloat162float(h));
    }
}

// ---------------------------------------------------------------------------
// bf16x3 GEMM via mma.sync: C[M,N] = A[M,K] @ Wt[N,K]^T + bias
// CTA tile 128x128, 8 warps (4m x 2n), warp tile 32x64 (2 x 8 mma tiles).
// K chunk 32, 3-stage cp.async pipeline.
// Smem stage = 4 tiles (Ahi, Alo, Bhi, Blo), each 128 rows x 80B (32 bf16 + pad).
// 80B row stride => (5m+c) mod 8 full cycle => conflict-free ldmatrix.
// ---------------------------------------------------------------------------
#define TILE_B  10240              // 128 * 80
#define STAGE_B (4 * TILE_B)       // 40960
#define GEMM_SMEM (3 * STAGE_B)    // 122880

__global__ __launch_bounds__(256) void gemm_mma(
    const __nv_bfloat16* __restrict__ Ahi, const __nv_bfloat16* __restrict__ Alo,
    const __nv_bfloat16* __restrict__ Bhi, const __nv_bfloat16* __restrict__ Blo,
    const float* __restrict__ bias, float* __restrict__ C)
{
    extern __shared__ char smem[];
    const int tid  = threadIdx.x;
    const int wid  = tid >> 5, lane = tid & 31;
    const int wm   = wid >> 1, wn = wid & 1;
    const int rowBase = blockIdx.y * 128;
    const int colBase = blockIdx.x * 128;
    const uint32_t smBase = smem_u32(smem);

    float acc[2][8][4];
#pragma unroll
    for (int i = 0; i < 2; i++)
#pragma unroll
        for (int j = 0; j < 8; j++)
#pragma unroll
            for (int k = 0; k < 4; k++) acc[i][j][k] = 0.f;

    // Global->smem load mapping: thread handles 32B (2 chunks) of one row per tile.
    const int ld_row = tid >> 1;               // 0..127
    const int ld_c0  = (tid & 1) * 2;          // chunk 0 or 2 (16B chunks)
    const size_t gA_off = (size_t)(rowBase + ld_row) * H_ + ld_c0 * 8;
    const size_t gB_off = (size_t)(colBase + ld_row) * H_ + ld_c0 * 8;
    const uint32_t st_off = ld_row * 80 + ld_c0 * 16;

    // ldmatrix per-lane base offsets
    const int lrow = lane & 15;
    const int lhi  = (lane >> 4) * 16;         // +16B for k 8..15 half
    uint32_t aoff[2], boff[4];
#pragma unroll
    for (int mt = 0; mt < 2; mt++) aoff[mt] = (wm * 32 + mt * 16 + lrow) * 80 + lhi;
#pragma unroll
    for (int g = 0; g < 4; g++)    boff[g]  = (wn * 64 + g * 16 + lrow) * 80 + lhi;

    const int KCH = H_ / 32;   // 32 chunks

    // --- pipeline: issue stage s for chunk s ---
#pragma unroll
    for (int s = 0; s < 2; s++) {
        const int kb = s * 32;
        uint32_t sb = smBase + s * STAGE_B + st_off;
        const __nv_bfloat16* pa  = Ahi + gA_off + kb;
        const __nv_bfloat16* pal = Alo + gA_off + kb;
        const __nv_bfloat16* pb  = Bhi + gB_off + kb;
        const __nv_bfloat16* pbl = Blo + gB_off + kb;
        CP16(sb,                 pa);  CP16(sb + 16,              pa + 8);
        CP16(sb + TILE_B,        pal); CP16(sb + TILE_B + 16,     pal + 8);
        CP16(sb + 2 * TILE_B,    pb);  CP16(sb + 2 * TILE_B + 16, pb + 8);
        CP16(sb + 3 * TILE_B,    pbl); CP16(sb + 3 * TILE_B + 16, pbl + 8);
        CP_COMMIT();
    }

    for (int cur = 0; cur < KCH; cur++) {
        CP_WAIT1();
        __syncthreads();

        const int nxt = cur + 2;
        if (nxt < KCH) {
            const int kb = nxt * 32;
            uint32_t sb = smBase + (nxt % 3) * STAGE_B + st_off;
            const __nv_bfloat16* pa  = Ahi + gA_off + kb;
            const __nv_bfloat16* pal = Alo + gA_off + kb;
            const __nv_bfloat16* pb  = Bhi + gB_off + kb;
            const __nv_bfloat16* pbl = Blo + gB_off + kb;
            CP16(sb,                 pa);  CP16(sb + 16,              pa + 8);
            CP16(sb + TILE_B,        pal); CP16(sb + TILE_B + 16,     pal + 8);
            CP16(sb + 2 * TILE_B,    pb);  CP16(sb + 2 * TILE_B + 16, pb + 8);
            CP16(sb + 3 * TILE_B,    pbl); CP16(sb + 3 * TILE_B + 16, pbl + 8);
        }
        CP_COMMIT();

        // --- compute chunk cur from buffer cur%3 ---
        const uint32_t s0 = smBase + (cur % 3) * STAGE_B;
#pragma unroll
        for (int ks = 0; ks < 2; ks++) {
            const uint32_t ko = ks * 32;
            uint32_t Ah[2][4], Al[2][4], Bh[4][4], Bl[4][4];
#pragma unroll
            for (int mt = 0; mt < 2; mt++) {
                LDSM4(Ah[mt], s0 + aoff[mt] + ko);
                LDSM4(Al[mt], s0 + TILE_B + aoff[mt] + ko);
            }
#pragma unroll
            for (int g = 0; g < 4; g++) {
                LDSM4(Bh[g], s0 + 2 * TILE_B + boff[g] + ko);
                LDSM4(Bl[g], s0 + 3 * TILE_B + boff[g] + ko);
            }
#pragma unroll
            for (int mt = 0; mt < 2; mt++)
#pragma unroll
                for (int nt = 0; nt < 8; nt++) {
                    const int g = nt >> 1, s = nt & 1;
                    MMA_BF16(acc[mt][nt], Ah[mt], Bh[g][s], Bh[g][s + 2]);
                    MMA_BF16(acc[mt][nt], Ah[mt], Bl[g][s], Bl[g][s + 2]);
                    MMA_BF16(acc[mt][nt], Al[mt], Bh[g][s], Bh[g][s + 2]);
                }
        }
    }

    // --- epilogue: bias add + store ---
    const int erow = lane >> 2;
    const int ecol = (lane & 3) * 2;
#pragma unroll
    for (int mt = 0; mt < 2; mt++) {
        const int r0 = rowBase + wm * 32 + mt * 16 + erow;
#pragma unroll
        for (int nt = 0; nt < 8; nt++) {
            const int col = colBase + wn * 64 + nt * 8 + ecol;
            const float bv0 = bias[col], bv1 = bias[col + 1];
            float2 v0, v1;
            v0.x = acc[mt][nt][0] + bv0; v0.y = acc[mt][nt][1] + bv1;
            v1.x = acc[mt][nt][2] + bv0; v1.y = acc[mt][nt][3] + bv1;
            *(float2*)&C[(size_t)r0 * H_ + col]       = v0;
            *(float2*)&C[(size_t)(r0 + 8) * H_ + col] = v1;
        }
    }
}

// ---------------------------------------------------------------------------
// Flash attention (fp32): unchanged (round-4 target).
// ---------------------------------------------------------------------------
__global__ __launch_bounds__(64) void attn_kernel(
    const float* __restrict__ Q, const float* __restrict__ K,
    const float* __restrict__ V, const float* __restrict__ mask,
    float* __restrict__ CTX)
{
    const int b = blockIdx.z;
    const int h = blockIdx.y;
    const int t = threadIdx.x;
    const int q = blockIdx.x * 64 + t;

    __shared__ float ks[64][64];
    __shared__ float vs[64][64];
    __shared__ float mk[64];

    const float* qp = Q + (size_t)(b * S_ + q) * H_ + h * HD_;
    float qv[64];
#pragma unroll
    for (int d = 0; d < 64; d += 4) {
        float4 f = *(const float4*)(qp + d);
        qv[d] = f.x; qv[d + 1] = f.y; qv[d + 2] = f.z; qv[d + 3] = f.w;
    }

    float m = -1e30f, l = 0.f;
    float acc[64];
#pragma unroll
    for (int d = 0; d < 64; d++) acc[d] = 0.f;

    const float* kbase = K + (size_t)(b * S_) * H_ + h * HD_;
    const float* vbase = V + (size_t)(b * S_) * H_ + h * HD_;

    for (int k0 = 0; k0 < S_; k0 += 64) {
        __syncthreads();
        const float* krow = kbase + (size_t)(k0 + t) * H_;
        const float* vrow = vbase + (size_t)(k0 + t) * H_;
#pragma unroll
        for (int d = 0; d < 64; d += 4) {
            *(float4*)&ks[t][d] = *(const float4*)(krow + d);
            *(float4*)&vs[t][d] = *(const float4*)(vrow + d);
        }
        mk[t] = mask[b * S_ + k0 + t];
        __syncthreads();

        for (int j = 0; j < 64; j++) {
            float s0 = 0.f, s1 = 0.f, s2 = 0.f, s3 = 0.f;
#pragma unroll
            for (int d = 0; d < 64; d += 4) {
                s0 = fmaf(qv[d],     ks[j][d],     s0);
                s1 = fmaf(qv[d + 1], ks[j][d + 1], s1);
                s2 = fmaf(qv[d + 2], ks[j][d + 2], s2);
                s3 = fmaf(qv[d + 3], ks[j][d + 3], s3);
            }
            float s = (s0 + s1) + (s2 + s3);
            s = s * 0.125f + mk[j];

            if (s > m) {
                float cor = __expf(m - s);
                l *= cor;
#pragma unroll
                for (int d = 0; d < 64; d++) acc[d] *= cor;
                m = s;
            }
            float p = __expf(s - m);
            l += p;
#pragma unroll
            for (int d = 0; d < 64; d++)
                acc[d] = fmaf(p, vs[j][d], acc[d]);
        }
    }

    float inv = 1.f / l;
    float* op = CTX + (size_t)(b * S_ + q) * H_ + h * HD_;
#pragma unroll
    for (int d = 0; d < 64; d += 4) {
        float4 o;
        o.x = acc[d] * inv; o.y = acc[d + 1] * inv;
        o.z = acc[d + 2] * inv; o.w = acc[d + 3] * inv;
        *(float4*)(op + d) = o;
    }
}

// ---------------------------------------------------------------------------
// Residual add + LayerNorm (eps 1e-12).
// ---------------------------------------------------------------------------
__device__ __forceinline__ float warp_sum(float v) {
#pragma unroll
    for (int o = 16; o > 0; o >>= 1) v += __shfl_xor_sync(0xffffffffu, v, o);
    return v;
}

__global__ __launch_bounds__(256) void resid_ln(
    const float* __restrict__ X, const float* __restrict__ R,
    const float* __restrict__ gamma, const float* __restrict__ beta,
    float* __restrict__ out)
{
    const int row = blockIdx.x;
    const int t = threadIdx.x;
    const float* x = X + (size_t)row * H_;
    const float* r = R + (size_t)row * H_;

    float4 xv = *(const float4*)(x + t * 4);
    float4 rv = *(const float4*)(r + t * 4);
    float v[4] = { xv.x + rv.x, xv.y + rv.y, xv.z + rv.z, xv.w + rv.w };

    float s = v[0] + v[1] + v[2] + v[3];
    float s2 = v[0] * v[0] + v[1] * v[1] + v[2] * v[2] + v[3] * v[3];

    __shared__ float red1[8], red2[8];
    float ws = warp_sum(s), ws2 = warp_sum(s2);
    int wid = t >> 5, lid = t & 31;
    if (lid == 0) { red1[wid] = ws; red2[wid] = ws2; }
    __syncthreads();
    if (wid == 0) {
        float a = (lid < 8) ? red1[lid] : 0.f;
        float b2 = (lid < 8) ? red2[lid] : 0.f;
        a = warp_sum(a); b2 = warp_sum(b2);
        if (lid == 0) { red1[0] = a; red2[0] = b2; }
    }
    __syncthreads();

    float mean = red1[0] * (1.f / H_);
    float var = red2[0] * (1.f / H_) - mean * mean;
    float rstd = rsqrtf(var + 1e-12f);

    float4 g4 = *(const float4*)(gamma + t * 4);
    float4 b4 = *(const float4*)(beta + t * 4);
    float4 o;
    o.x = (v[0] - mean) * rstd * g4.x + b4.x;
    o.y = (v[1] - mean) * rstd * g4.y + b4.y;
    o.z = (v[2] - mean) * rstd * g4.z + b4.z;
    o.w = (v[3] - mean) * rstd * g4.w + b4.w;
    *(float4*)(out + (size_t)row * H_ + t * 4) = o;
}

// ---------------------------------------------------------------------------
// Launch
// ---------------------------------------------------------------------------
extern "C" void kernel_launch(void* const* d_in, const int* in_sizes, int n_in,
                              void* d_out, int out_size)
{
    const float* hidden = (const float*)d_in[0];
    const float* mask   = (const float*)d_in[1];
    const float* Wq = (const float*)d_in[2];
    const float* bq = (const float*)d_in[3];
    const float* Wk = (const float*)d_in[4];
    const float* bk = (const float*)d_in[5];
    const float* Wv = (const float*)d_in[6];
    const float* bv = (const float*)d_in[7];
    const float* Wo = (const float*)d_in[8];
    const float* bo = (const float*)d_in[9];
    const float* gamma = (const float*)d_in[10];
    const float* beta  = (const float*)d_in[11];
    float* out = (float*)d_out;

    float *Q, *K, *V, *CTX, *O;
    __nv_bfloat16 *Ahi, *Alo, *Whi, *Wlo;
    cudaGetSymbolAddress((void**)&Q,   g_Q);
    cudaGetSymbolAddress((void**)&K,   g_K);
    cudaGetSymbolAddress((void**)&V,   g_V);
    cudaGetSymbolAddress((void**)&CTX, g_CTX);
    cudaGetSymbolAddress((void**)&O,   g_O);
    cudaGetSymbolAddress((void**)&Ahi, g_Ahi);
    cudaGetSymbolAddress((void**)&Alo, g_Alo);
    cudaGetSymbolAddress((void**)&Whi, g_Whi);
    cudaGetSymbolAddress((void**)&Wlo, g_Wlo);

    static bool attr_set = false;
    if (!attr_set) {
        cudaFuncSetAttribute(gemm_mma, cudaFuncAttributeMaxDynamicSharedMemorySize, GEMM_SMEM);
        attr_set = true;
    }

    dim3 ggrid(H_ / 128, ROWS_ / 128);        // (8, 32)
    dim3 tgrid(H_ / 32, H_ / 32);             // (32, 32)
    dim3 tblk(32, 8);
    const int n4 = ROWS_ * H_ / 4;

    // hidden -> bf16 hi/lo (once)
    split_fp32<<<(n4 + 255) / 256, 256>>>(hidden, Ahi, Alo, n4);

    // Q = hidden @ Wq + bq
    split_transpose<<<tgrid, tblk>>>(Wq, Whi, Wlo);
    gemm_mma<<<ggrid, 256, GEMM_SMEM>>>(Ahi, Alo, Whi, Wlo, bq, Q);
    // K
    split_transpose<<<tgrid, tblk>>>(Wk, Whi, Wlo);
    gemm_mma<<<ggrid, 256, GEMM_SMEM>>>(Ahi, Alo, Whi, Wlo, bk, K);
    // V
    split_transpose<<<tgrid, tblk>>>(Wv, Whi, Wlo);
    gemm_mma<<<ggrid, 256, GEMM_SMEM>>>(Ahi, Alo, Whi, Wlo, bv, V);

    // Attention
    dim3 agrid(S_ / 64, NH_, B_);
    attn_kernel<<<agrid, 64>>>(Q, K, V, mask, CTX);

    // O = CTX @ Wo + bo
    split_fp32<<<(n4 + 255) / 256, 256>>>(CTX, Ahi, Alo, n4);
    split_transpose<<<tgrid, tblk>>>(Wo, Whi, Wlo);
    gemm_mma<<<ggrid, 256, GEMM_SMEM>>>(Ahi, Alo, Whi, Wlo, bo, O);

    // residual + LN
    resid_ln<<<ROWS_, 256>>>(O, hidden, gamma, beta, out);
}

// round 4
// speedup vs baseline: 7.1540x; 6.1550x over previous
#include <cuda_runtime.h>
#include <cuda_fp16.h>
#include <math.h>
#include <stdint.h>

// Problem constants
#define B_  2
#define S_  2048
#define H_  1024
#define NH_ 16
#define HD_ 64
#define ROWS_ (B_ * S_)          // 4096

// Scratch (device globals: allocation-free)
__device__ __half g_Xh [ROWS_ * H_];     // hidden fp16
__device__ __half g_Wh [4 * H_ * H_];    // Wt q,k,v,o fp16 [n][k]
__device__ __half g_Qh [ROWS_ * H_];
__device__ __half g_Kh [ROWS_ * H_];
__device__ __half g_Vt [ROWS_ * H_];     // [(b*NH+h)*HD + d][S]
__device__ __half g_CTXh[ROWS_ * H_];
__device__ float  g_O  [ROWS_ * H_];

// ---------------------------------------------------------------------------
// PTX helpers
// ---------------------------------------------------------------------------
__device__ __forceinline__ uint32_t smem_u32(const void* p) {
    uint32_t a;
    asm("{ .reg .u64 t; cvta.to.shared.u64 t, %1; cvt.u32.u64 %0, t; }" : "=r"(a) : "l"(p));
    return a;
}
#define CP16(dst, src) \
    asm volatile("cp.async.cg.shared.global [%0], [%1], 16;" :: "r"(dst), "l"(src))
#define CP_COMMIT() asm volatile("cp.async.commit_group;" ::: "memory")
#define CP_WAIT0()  asm volatile("cp.async.wait_group 0;" ::: "memory")
#define CP_WAIT1()  asm volatile("cp.async.wait_group 1;" ::: "memory")

#define LDSM4(r, a) \
    asm volatile("ldmatrix.sync.aligned.m8n8.x4.shared.b16 {%0,%1,%2,%3}, [%4];" \
                 : "=r"((r)[0]), "=r"((r)[1]), "=r"((r)[2]), "=r"((r)[3]) : "r"(a))

#define MMA_F16(d, a, b0, b1) \
    asm volatile("mma.sync.aligned.m16n8k16.row.col.f32.f16.f16.f32 " \
                 "{%0,%1,%2,%3}, {%4,%5,%6,%7}, {%8,%9}, {%0,%1,%2,%3};" \
                 : "+f"((d)[0]), "+f"((d)[1]), "+f"((d)[2]), "+f"((d)[3]) \
                 : "r"((a)[0]), "r"((a)[1]), "r"((a)[2]), "r"((a)[3]), "r"(b0), "r"(b1))

__device__ __forceinline__ uint32_t f22h2(float a, float b) {
    __half2 h = __floats2half2_rn(a, b);
    return *(uint32_t*)&h;
}

// ---------------------------------------------------------------------------
// fp32 -> fp16 convert (vector of 8)
// ---------------------------------------------------------------------------
__global__ __launch_bounds__(256) void conv_h(
    const float* __restrict__ X, __half* __restrict__ Y, int n8)
{
    int i = blockIdx.x * blockDim.x + threadIdx.x;
    if (i >= n8) return;
    float4 a = *(const float4*)(X + i * 8);
    float4 b = *(const float4*)(X + i * 8 + 4);
    __half2 h[4];
    h[0] = __floats2half2_rn(a.x, a.y);
    h[1] = __floats2half2_rn(a.z, a.w);
    h[2] = __floats2half2_rn(b.x, b.y);
    h[3] = __floats2half2_rn(b.z, b.w);
    *(uint4*)(Y + i * 8) = *(uint4*)h;
}

// ---------------------------------------------------------------------------
// Transpose+convert all 4 weight matrices: W[K][N] fp32 -> Wt[z*H + n][k] fp16
// ---------------------------------------------------------------------------
__global__ __launch_bounds__(256) void convT(
    const float* __restrict__ W0, const float* __restrict__ W1,
    const float* __restrict__ W2, const float* __restrict__ W3,
    __half* __restrict__ T)
{
    __shared__ float t[32][33];
    const float* W = (blockIdx.z == 0) ? W0 : (blockIdx.z == 1) ? W1 :
                     (blockIdx.z == 2) ? W2 : W3;
    const int n0 = blockIdx.x * 32, k0 = blockIdx.y * 32;
    const int tx = threadIdx.x, ty = threadIdx.y;   // (32, 8)
#pragma unroll
    for (int r = 0; r < 32; r += 8)
        t[ty + r][tx] = W[(size_t)(k0 + ty + r) * H_ + n0 + tx];
    __syncthreads();
#pragma unroll
    for (int r = 0; r < 32; r += 8) {
        int n = n0 + ty + r, k = k0 + tx;
        T[((size_t)blockIdx.z * H_ + n) * H_ + k] = __float2half(t[tx][ty + r]);
    }
}

// ---------------------------------------------------------------------------
// fp16 GEMM mainloop: acc[2][8][4] += A[128,K-tile] @ B[128,K-tile]^T
// CTA 128x128, 8 warps (4m x 2n), K chunk 32, 3-stage cp.async pipeline.
// Smem tile: 128 rows x 80B (32 half + 16B pad) -> conflict-free ldmatrix.
// ---------------------------------------------------------------------------
#define TILE_B  10240              // 128 * 80
#define STAGE_B (2 * TILE_B)       // 20480
#define GEMM_SMEM (3 * STAGE_B)    // 61440

__device__ __forceinline__ void gemm_mainloop(
    const __half* __restrict__ A, const __half* __restrict__ Bm,
    int rowBase, int colBase, char* smem, float acc[2][8][4])
{
    const int tid  = threadIdx.x;
    const int lane = tid & 31, wid = tid >> 5;
    const int wm   = wid >> 1, wn = wid & 1;
    const uint32_t smBase = smem_u32(smem);

    const int ld_row = tid >> 1;
    const int ld_c0  = (tid & 1) * 2;
    const size_t gA_off = (size_t)(rowBase + ld_row) * H_ + ld_c0 * 8;
    const size_t gB_off = (size_t)(colBase + ld_row) * H_ + ld_c0 * 8;
    const uint32_t st_off = ld_row * 80 + ld_c0 * 16;

    const int lrow = lane & 15;
    const int lhi  = (lane >> 4) * 16;
    uint32_t aoff[2], boff[4];
#pragma unroll
    for (int mt = 0; mt < 2; mt++) aoff[mt] = (wm * 32 + mt * 16 + lrow) * 80 + lhi;
#pragma unroll
    for (int g = 0; g < 4; g++)    boff[g]  = (wn * 64 + g * 16 + lrow) * 80 + lhi;

    const int KCH = H_ / 32;

#pragma unroll
    for (int s = 0; s < 2; s++) {
        const int kb = s * 32;
        uint32_t sb = smBase + s * STAGE_B + st_off;
        const __half* pa = A  + gA_off + kb;
        const __half* pb = Bm + gB_off + kb;
        CP16(sb,          pa); CP16(sb + 16,          pa + 8);
        CP16(sb + TILE_B, pb); CP16(sb + TILE_B + 16, pb + 8);
        CP_COMMIT();
    }

    for (int cur = 0; cur < KCH; cur++) {
        CP_WAIT1();
        __syncthreads();

        const int nxt = cur + 2;
        if (nxt < KCH) {
            const int kb = nxt * 32;
            uint32_t sb = smBase + (nxt % 3) * STAGE_B + st_off;
            const __half* pa = A  + gA_off + kb;
            const __half* pb = Bm + gB_off + kb;
            CP16(sb,          pa); CP16(sb + 16,          pa + 8);
            CP16(sb + TILE_B, pb); CP16(sb + TILE_B + 16, pb + 8);
        }
        CP_COMMIT();

        const uint32_t s0 = smBase + (cur % 3) * STAGE_B;
#pragma unroll
        for (int ks = 0; ks < 2; ks++) {
            const uint32_t ko = ks * 32;
            uint32_t Ah[2][4], Bh[4][4];
#pragma unroll
            for (int mt = 0; mt < 2; mt++) LDSM4(Ah[mt], s0 + aoff[mt] + ko);
#pragma unroll
            for (int g = 0; g < 4; g++)    LDSM4(Bh[g], s0 + TILE_B + boff[g] + ko);
#pragma unroll
            for (int mt = 0; mt < 2; mt++)
#pragma unroll
                for (int nt = 0; nt < 8; nt++) {
                    const int g = nt >> 1, ss = nt & 1;
                    MMA_F16(acc[mt][nt], Ah[mt], Bh[g][ss], Bh[g][ss + 2]);
                }
        }
    }
}

// ---------------------------------------------------------------------------
// Fused QKV GEMM: A=Xh [4096,1024], B=Wt[3072][1024]. Output per n-range:
//   n in [0,1024)    -> Qh fp16 [row][H]
//   n in [1024,2048) -> Kh fp16 [row][H]
//   n in [2048,3072) -> Vt fp16 transposed per head
// ---------------------------------------------------------------------------
__global__ __launch_bounds__(256) void gemm_qkv(
    const __half* __restrict__ A, const __half* __restrict__ Wt,
    const float* __restrict__ bq, const float* __restrict__ bk,
    const float* __restrict__ bv,
    __half* __restrict__ Qh, __half* __restrict__ Kh, __half* __restrict__ Vt)
{
    extern __shared__ char smem[];
    const int rowBase = blockIdx.y * 128;
    const int colBase = blockIdx.x * 128;   // 0..2944

    float acc[2][8][4];
#pragma unroll
    for (int i = 0; i < 2; i++)
#pragma unroll
        for (int j = 0; j < 8; j++)
#pragma unroll
            for (int k = 0; k < 4; k++) acc[i][j][k] = 0.f;

    gemm_mainloop(A, Wt, rowBase, colBase, smem, acc);

    const int lane = threadIdx.x & 31, wid = threadIdx.x >> 5;
    const int wm = wid >> 1, wn = wid & 1;
    const int erow = lane >> 2, ecol = (lane & 3) * 2;
    const int sel  = colBase >> 10;
    const int colM = colBase & 1023;
    const float* bias = (sel == 0) ? bq : (sel == 1) ? bk : bv;

#pragma unroll
    for (int mt = 0; mt < 2; mt++) {
        const int r0 = rowBase + wm * 32 + mt * 16 + erow;
#pragma unroll
        for (int nt = 0; nt < 8; nt++) {
            const int col = colM + wn * 64 + nt * 8 + ecol;
            const float b0 = bias[col], b1 = bias[col + 1];
            float v00 = acc[mt][nt][0] + b0, v01 = acc[mt][nt][1] + b1;
            float v10 = acc[mt][nt][2] + b0, v11 = acc[mt][nt][3] + b1;
            if (sel < 2) {
                __half* C = sel ? Kh : Qh;
                *(uint32_t*)&C[(size_t)r0 * H_ + col]       = f22h2(v00, v01);
                *(uint32_t*)&C[(size_t)(r0 + 8) * H_ + col] = f22h2(v10, v11);
            } else {
                const int h = col >> 6, d = col & 63;
                const int b_  = r0 >> 11;
                const int s0_ = r0 & 2047;
                size_t base0 = ((size_t)(b_ * NH_ + h) * HD_ + d) * S_;
                Vt[base0 + s0_]          = __float2half(v00);
                Vt[base0 + S_ + s0_]     = __float2half(v01);
                Vt[base0 + s0_ + 8]      = __float2half(v10);
                Vt[base0 + S_ + s0_ + 8] = __float2half(v11);
            }
        }
    }
}

// ---------------------------------------------------------------------------
// Output-proj GEMM: A=CTXh, B=Wt_o -> fp32 C + bias
// ---------------------------------------------------------------------------
__global__ __launch_bounds__(256) void gemm_out(
    const __half* __restrict__ A, const __half* __restrict__ Wt,
    const float* __restrict__ bias, float* __restrict__ C)
{
    extern __shared__ char smem[];
    const int rowBase = blockIdx.y * 128;
    const int colBase = blockIdx.x * 128;

    float acc[2][8][4];
#pragma unroll
    for (int i = 0; i < 2; i++)
#pragma unroll
        for (int j = 0; j < 8; j++)
#pragma unroll
            for (int k = 0; k < 4; k++) acc[i][j][k] = 0.f;

    gemm_mainloop(A, Wt, rowBase, colBase, smem, acc);

    const int lane = threadIdx.x & 31, wid = threadIdx.x >> 5;
    const int wm = wid >> 1, wn = wid & 1;
    const int erow = lane >> 2, ecol = (lane & 3) * 2;

#pragma unroll
    for (int mt = 0; mt < 2; mt++) {
        const int r0 = rowBase + wm * 32 + mt * 16 + erow;
#pragma unroll
        for (int nt = 0; nt < 8; nt++) {
            const int col = colBase + wn * 64 + nt * 8 + ecol;
            const float b0 = bias[col], b1 = bias[col + 1];
            float2 v0, v1;
            v0.x = acc[mt][nt][0] + b0; v0.y = acc[mt][nt][1] + b1;
            v1.x = acc[mt][nt][2] + b0; v1.y = acc[mt][nt][3] + b1;
            *(float2*)&C[(size_t)r0 * H_ + col]       = v0;
            *(float2*)&C[(size_t)(r0 + 8) * H_ + col] = v1;
        }
    }
}

// ---------------------------------------------------------------------------
// fp16 tensor-core flash attention.
// CTA: 128 queries x one (b,h). 4 warps, warp = 32 query rows.
// K/V tiles of 64 keys double-buffered via cp.async. V pre-transposed [d][s].
// Smem rows padded to 144B (72 halves) -> conflict-free ldmatrix.
// ---------------------------------------------------------------------------
#define AQ_OFF 0                       // Q: 128*144 = 18432
#define AK_OFF 18432                   // K: 2 * 64*144 = 18432
#define AV_OFF (18432 + 18432)         // V: 2 * 9216
#define AM_OFF (18432 + 2 * 18432)     // mask: 2 * 256B
#define ATTN_SMEM (AM_OFF + 512)

__global__ __launch_bounds__(128) void attn_f16(
    const __half* __restrict__ Qh, const __half* __restrict__ Kh,
    const __half* __restrict__ Vt, const float* __restrict__ mask,
    __half* __restrict__ CTXh)
{
    extern __shared__ char smem[];
    const int tid = threadIdx.x, lane = tid & 31, wid = tid >> 5;
    const int qb = blockIdx.x * 128, h = blockIdx.y, b = blockIdx.z;
    const uint32_t sm = smem_u32(smem);

    const __half* Qg = Qh + ((size_t)(b * S_ + qb)) * H_ + h * HD_;
    const __half* Kg = Kh + ((size_t)(b * S_)) * H_ + h * HD_;
    const __half* Vg = Vt + ((size_t)((b * NH_ + h) * HD_)) * S_;
    const float*  Mg = mask + b * S_;

    // ---- prologue: Q tile + K/V/mask tile 0 ----
    {
        const char* src = (const char*)(Qg + (size_t)tid * H_);
        uint32_t dst = sm + AQ_OFF + tid * 144;
#pragma unroll
        for (int c = 0; c < 8; c++) CP16(dst + c * 16, src + c * 16);
    }
    {
        const int r = tid >> 1, c0 = (tid & 1) * 4;
        const char* ks = (const char*)(Kg + (size_t)r * H_) + c0 * 16;
        const char* vs = (const char*)(Vg + (size_t)r * S_) + c0 * 16;
        uint32_t kd = sm + AK_OFF + r * 144 + c0 * 16;
        uint32_t vd = sm + AV_OFF + r * 144 + c0 * 16;
#pragma unroll
        for (int c = 0; c < 4; c++) { CP16(kd + c * 16, ks + c * 32 / 2); }
#pragma unroll
        for (int c = 0; c < 4; c++) { CP16(vd + c * 16, vs + c * 16); }
    }
    if (tid < 16) CP16(sm + AM_OFF + tid * 16, (const char*)Mg + tid * 16);
    CP_COMMIT();
    CP_WAIT0();
    __syncthreads();

    // ---- Q fragments (held for whole kernel) ----
    const int lrow = lane & 15;
    const int lhi  = (lane >> 4) * 16;
    uint32_t Qf[2][4][4];
#pragma unroll
    for (int mt = 0; mt < 2; mt++)
#pragma unroll
        for (int kk = 0; kk < 4; kk++)
            LDSM4(Qf[mt][kk], sm + AQ_OFF + (wid * 32 + mt * 16 + lrow) * 144 + kk * 32 + lhi);

    float O[2][8][4];
#pragma unroll
    for (int mt = 0; mt < 2; mt++)
#pragma unroll
        for (int j = 0; j < 8; j++)
#pragma unroll
            for (int k = 0; k < 4; k++) O[mt][j][k] = 0.f;
    float mrow[2][2] = {{-1e30f, -1e30f}, {-1e30f, -1e30f}};
    float lrow_[2][2] = {{0.f, 0.f}, {0.f, 0.f}};

    const int NKT = S_ / 64;   // 32
    for (int kt = 0; kt < NKT; kt++) {
        const int buf = kt & 1;

        // issue next tile into buf^1
        if (kt + 1 < NKT) {
            const int k0n = (kt + 1) * 64;
            const int nb = buf ^ 1;
            const int r = tid >> 1, c0 = (tid & 1) * 4;
            const char* ks = (const char*)(Kg + (size_t)(k0n + r) * H_) + c0 * 16;
            const char* vs = (const char*)(Vg + (size_t)r * S_ + k0n) + c0 * 16;
            uint32_t kd = sm + AK_OFF + nb * 9216 + r * 144 + c0 * 16;
            uint32_t vd = sm + AV_OFF + nb * 9216 + r * 144 + c0 * 16;
#pragma unroll
            for (int c = 0; c < 4; c++) CP16(kd + c * 16, ks + c * 16);
#pragma unroll
            for (int c = 0; c < 4; c++) CP16(vd + c * 16, vs + c * 16);
            if (tid < 16)
                CP16(sm + AM_OFF + nb * 256 + tid * 16,
                     (const char*)(Mg + k0n) + tid * 16);
        }
        CP_COMMIT();
        CP_WAIT1();
        __syncthreads();

        const uint32_t skb = sm + AK_OFF + buf * 9216;
        const uint32_t svb = sm + AV_OFF + buf * 9216;
        const float* mk = (const float*)(smem + AM_OFF + buf * 256);
        const int c0 = (lane & 3) * 2;

#pragma unroll
        for (int mt = 0; mt < 2; mt++) {
            float Sf[8][4];
#pragma unroll
            for (int j = 0; j < 8; j++)
#pragma unroll
                for (int k = 0; k < 4; k++) Sf[j][k] = 0.f;

            // S = Q K^T
#pragma unroll
            for (int g = 0; g < 4; g++) {
                uint32_t KB[4][4];
#pragma unroll
                for (int kk = 0; kk < 4; kk++)
                    LDSM4(KB[kk], skb + (g * 16 + lrow) * 144 + kk * 32 + lhi);
#pragma unroll
                for (int ss = 0; ss < 2; ss++) {
                    const int nt = g * 2 + ss;
#pragma unroll
                    for (int kk = 0; kk < 4; kk++)
                        MMA_F16(Sf[nt], Qf[mt][kk], KB[kk][ss], KB[kk][ss + 2]);
                }
            }

            // scale + mask + online softmax
            float x0 = -1e30f, x1 = -1e30f;
#pragma unroll
            for (int j = 0; j < 8; j++) {
                const float m0 = mk[j * 8 + c0], m1 = mk[j * 8 + c0 + 1];
                Sf[j][0] = Sf[j][0] * 0.125f + m0;
                Sf[j][1] = Sf[j][1] * 0.125f + m1;
                Sf[j][2] = Sf[j][2] * 0.125f + m0;
                Sf[j][3] = Sf[j][3] * 0.125f + m1;
                x0 = fmaxf(x0, fmaxf(Sf[j][0], Sf[j][1]));
                x1 = fmaxf(x1, fmaxf(Sf[j][2], Sf[j][3]));
            }
            x0 = fmaxf(x0, __shfl_xor_sync(0xffffffffu, x0, 1));
            x0 = fmaxf(x0, __shfl_xor_sync(0xffffffffu, x0, 2));
            x1 = fmaxf(x1, __shfl_xor_sync(0xffffffffu, x1, 1));
            x1 = fmaxf(x1, __shfl_xor_sync(0xffffffffu, x1, 2));

            const float mn0 = fmaxf(mrow[mt][0], x0);
            const float mn1 = fmaxf(mrow[mt][1], x1);
            const float cor0 = __expf(mrow[mt][0] - mn0);
            const float cor1 = __expf(mrow[mt][1] - mn1);
            mrow[mt][0] = mn0; mrow[mt][1] = mn1;

            float rs0 = 0.f, rs1 = 0.f;
#pragma unroll
            for (int j = 0; j < 8; j++) {
                Sf[j][0] = __expf(Sf[j][0] - mn0);
                Sf[j][1] = __expf(Sf[j][1] - mn0);
                Sf[j][2] = __expf(Sf[j][2] - mn1);
                Sf[j][3] = __expf(Sf[j][3] - mn1);
                rs0 += Sf[j][0] + Sf[j][1];
                rs1 += Sf[j][2] + Sf[j][3];
            }
            rs0 += __shfl_xor_sync(0xffffffffu, rs0, 1);
            rs0 += __shfl_xor_sync(0xffffffffu, rs0, 2);
            rs1 += __shfl_xor_sync(0xffffffffu, rs1, 1);
            rs1 += __shfl_xor_sync(0xffffffffu, rs1, 2);
            lrow_[mt][0] = lrow_[mt][0] * cor0 + rs0;
            lrow_[mt][1] = lrow_[mt][1] * cor1 + rs1;

#pragma unroll
            for (int j = 0; j < 8; j++) {
                O[mt][j][0] *= cor0; O[mt][j][1] *= cor0;
                O[mt][j][2] *= cor1; O[mt][j][3] *= cor1;
            }

            // P fragments (A-frag layout from S accumulator layout)
            uint32_t P[4][4];
#pragma unroll
            for (int t = 0; t < 4; t++) {
                P[t][0] = f22h2(Sf[2 * t][0],     Sf[2 * t][1]);
                P[t][1] = f22h2(Sf[2 * t][2],     Sf[2 * t][3]);
                P[t][2] = f22h2(Sf[2 * t + 1][0], Sf[2 * t + 1][1]);
                P[t][3] = f22h2(Sf[2 * t + 1][2], Sf[2 * t + 1][3]);
            }

            // O += P @ V  (V as [d][key], B frags via plain ldmatrix)
#pragma unroll
            for (int g = 0; g < 4; g++) {
                uint32_t VB[4][4];
#pragma unroll
                for (int t = 0; t < 4; t++)
                    LDSM4(VB[t], svb + (g * 16 + lrow) * 144 + t * 32 + lhi);
#pragma unroll
                for (int ss = 0; ss < 2; ss++) {
                    const int nt = g * 2 + ss;
#pragma unroll
                    for (int t = 0; t < 4; t++)
                        MMA_F16(O[mt][nt], P[t], VB[t][ss], VB[t][ss + 2]);
                }
            }
        }
        __syncthreads();
    }

    // ---- epilogue: normalize, store CTX fp16 ----
    const int erow = lane >> 2, ecol = (lane & 3) * 2;
#pragma unroll
    for (int mt = 0; mt < 2; mt++) {
        const float i0 = 1.f / lrow_[mt][0];
        const float i1 = 1.f / lrow_[mt][1];
        const int r0 = qb + wid * 32 + mt * 16 + erow;
#pragma unroll
        for (int j = 0; j < 8; j++) {
            const int col = h * HD_ + j * 8 + ecol;
            *(uint32_t*)&CTXh[(size_t)(b * S_ + r0) * H_ + col] =
                f22h2(O[mt][j][0] * i0, O[mt][j][1] * i0);
            *(uint32_t*)&CTXh[(size_t)(b * S_ + r0 + 8) * H_ + col] =
                f22h2(O[mt][j][2] * i1, O[mt][j][3] * i1);
        }
    }
}

// ---------------------------------------------------------------------------
// Residual add + LayerNorm (eps 1e-12).
// ---------------------------------------------------------------------------
__device__ __forceinline__ float warp_sum(float v) {
#pragma unroll
    for (int o = 16; o > 0; o >>= 1) v += __shfl_xor_sync(0xffffffffu, v, o);
    return v;
}

__global__ __launch_bounds__(256) void resid_ln(
    const float* __restrict__ X, const float* __restrict__ R,
    const float* __restrict__ gamma, const float* __restrict__ beta,
    float* __restrict__ out)
{
    const int row = blockIdx.x;
    const int t = threadIdx.x;
    const float* x = X + (size_t)row * H_;
    const float* r = R + (size_t)row * H_;

    float4 xv = *(const float4*)(x + t * 4);
    float4 rv = *(const float4*)(r + t * 4);
    float v[4] = { xv.x + rv.x, xv.y + rv.y, xv.z + rv.z, xv.w + rv.w };

    float s = v[0] + v[1] + v[2] + v[3];
    float s2 = v[0] * v[0] + v[1] * v[1] + v[2] * v[2] + v[3] * v[3];

    __shared__ float red1[8], red2[8];
    float ws = warp_sum(s), ws2 = warp_sum(s2);
    int wid = t >> 5, lid = t & 31;
    if (lid == 0) { red1[wid] = ws; red2[wid] = ws2; }
    __syncthreads();
    if (wid == 0) {
        float a = (lid < 8) ? red1[lid] : 0.f;
        float b2 = (lid < 8) ? red2[lid] : 0.f;
        a = warp_sum(a); b2 = warp_sum(b2);
        if (lid == 0) { red1[0] = a; red2[0] = b2; }
    }
    __syncthreads();

    float mean = red1[0] * (1.f / H_);
    float var = red2[0] * (1.f / H_) - mean * mean;
    float rstd = rsqrtf(var + 1e-12f);

    float4 g4 = *(const float4*)(gamma + t * 4);
    float4 b4 = *(const float4*)(beta + t * 4);
    float4 o;
    o.x = (v[0] - mean) * rstd * g4.x + b4.x;
    o.y = (v[1] - mean) * rstd * g4.y + b4.y;
    o.z = (v[2] - mean) * rstd * g4.z + b4.z;
    o.w = (v[3] - mean) * rstd * g4.w + b4.w;
    *(float4*)(out + (size_t)row * H_ + t * 4) = o;
}

// ---------------------------------------------------------------------------
// Launch
// ---------------------------------------------------------------------------
extern "C" void kernel_launch(void* const* d_in, const int* in_sizes, int n_in,
                              void* d_out, int out_size)
{
    const float* hidden = (const float*)d_in[0];
    const float* mask   = (const float*)d_in[1];
    const float* Wq = (const float*)d_in[2];
    const float* bq = (const float*)d_in[3];
    const float* Wk = (const float*)d_in[4];
    const float* bk = (const float*)d_in[5];
    const float* Wv = (const float*)d_in[6];
    const float* bv = (const float*)d_in[7];
    const float* Wo = (const float*)d_in[8];
    const float* bo = (const float*)d_in[9];
    const float* gamma = (const float*)d_in[10];
    const float* beta  = (const float*)d_in[11];
    float* out = (float*)d_out;

    __half *Xh, *Wh, *Qh, *Kh, *Vt, *CTXh;
    float* O;
    cudaGetSymbolAddress((void**)&Xh,   g_Xh);
    cudaGetSymbolAddress((void**)&Wh,   g_Wh);
    cudaGetSymbolAddress((void**)&Qh,   g_Qh);
    cudaGetSymbolAddress((void**)&Kh,   g_Kh);
    cudaGetSymbolAddress((void**)&Vt,   g_Vt);
    cudaGetSymbolAddress((void**)&CTXh, g_CTXh);
    cudaGetSymbolAddress((void**)&O,    g_O);

    static bool attr_set = false;
    if (!attr_set) {
        cudaFuncSetAttribute(gemm_qkv, cudaFuncAttributeMaxDynamicSharedMemorySize, GEMM_SMEM);
        cudaFuncSetAttribute(gemm_out, cudaFuncAttributeMaxDynamicSharedMemorySize, GEMM_SMEM);
        cudaFuncSetAttribute(attn_f16, cudaFuncAttributeMaxDynamicSharedMemorySize, ATTN_SMEM);
        attr_set = true;
    }

    const int n8 = ROWS_ * H_ / 8;
    conv_h<<<(n8 + 255) / 256, 256>>>(hidden, Xh, n8);

    dim3 tgrid(H_ / 32, H_ / 32, 4);
    convT<<<tgrid, dim3(32, 8)>>>(Wq, Wk, Wv, Wo, Wh);

    dim3 qkvgrid(3 * H_ / 128, ROWS_ / 128);   // (24, 32)
    gemm_qkv<<<qkvgrid, 256, GEMM_SMEM>>>(Xh, Wh, bq, bk, bv, Qh, Kh, Vt);

    dim3 agrid(S_ / 128, NH_, B_);             // (16, 16, 2)
    attn_f16<<<agrid, 128, ATTN_SMEM>>>(Qh, Kh, Vt, mask, CTXh);

    dim3 ogrid(H_ / 128, ROWS_ / 128);         // (8, 32)
    gemm_out<<<ogrid, 256, GEMM_SMEM>>>(CTXh, Wh + 3 * (size_t)H_ * H_, bo, O);

    resid_ln<<<ROWS_, 256>>>(O, hidden, gamma, beta, out);
}